// round 1
// baseline (speedup 1.0000x reference)
#include <cuda_runtime.h>
#include <math.h>

// ---------------- scratch (device globals: allocation-free) ----------------
static __device__ float g_wr[1104 * 70];                   // renormed embed
static __device__ float g_e[(size_t)65536 * 70];           // e = x @ wr
static __device__ float g_xg[(size_t)65536 * 280];         // xg = e @ w_ih^T + b
static __device__ float g_hs[(size_t)65536 * 70];          // lstm hidden states
static __device__ float g_energy[65536];                   // attention energies

#define DEV_INLINE __device__ __forceinline__

// packed fp32x2 FMA (sm_100+): 2 MACs per issue vs 1 for plain FFMA
DEV_INLINE float2 ffma2(float2 a, float2 b, float2 c) {
    unsigned long long ua = *reinterpret_cast<unsigned long long*>(&a);
    unsigned long long ub = *reinterpret_cast<unsigned long long*>(&b);
    unsigned long long uc = *reinterpret_cast<unsigned long long*>(&c);
    unsigned long long ud;
    asm("fma.rn.f32x2 %0, %1, %2, %3;" : "=l"(ud) : "l"(ua), "l"(ub), "l"(uc));
    return *reinterpret_cast<float2*>(&ud);
}

DEV_INLINE float sigmoidf_(float x) { return 1.0f / (1.0f + __expf(-x)); }
DEV_INLINE float tanhf_(float x)    { return 2.0f / (1.0f + __expf(-2.0f * x)) - 1.0f; }

// ---------------- K0: renorm embed rows (max_norm=1) ----------------
__global__ void k_renorm(const float* __restrict__ ew) {
    int row = blockIdx.x * 8 + (threadIdx.x >> 5);   // 138*8 = 1104
    int lane = threadIdx.x & 31;
    const float* src = ew + row * 70;
    float s = 0.f;
    for (int k = lane; k < 70; k += 32) { float v = src[k]; s += v * v; }
    #pragma unroll
    for (int o = 16; o > 0; o >>= 1) s += __shfl_xor_sync(0xffffffffu, s, o);
    float n = sqrtf(s);
    float sc = (n > 1.0f) ? 1.0f / (n + 1e-7f) : 1.0f;
    float* dst = g_wr + row * 70;
    for (int k = lane; k < 70; k += 32) dst[k] = src[k] * sc;
}

// ---------------- K1: e = x(65536x1104) @ wr(1104x70), f32x2 inner ----------------
// BM=128, BN=72(pad), KT=16, 192 threads, thread tile 8x6 (4 row-pairs x 6 cols)
__global__ __launch_bounds__(192) void k_egemm(const float* __restrict__ x) {
    __shared__ float  sa[16][132];    // A^T tile [k][m], stride 132 (aligned + low conflict)
    __shared__ float2 sb[16][72];     // B tile, value DUPLICATED into both lanes
    const int tid = threadIdx.x;
    const int mb = blockIdx.x * 128;
    const int mg = tid / 12, ng = tid % 12;
    const int m0 = mg * 8, n0 = ng * 6;

    float2 acc[4][6];
    #pragma unroll
    for (int p = 0; p < 4; p++)
        #pragma unroll
        for (int j = 0; j < 6; j++) acc[p][j] = make_float2(0.f, 0.f);

    for (int kt = 0; kt < 1104; kt += 16) {
        // load A tile: 512 float4 (coalesced: 4 consecutive threads cover 64B of one row)
        for (int i = tid; i < 512; i += 192) {
            int m = i >> 2; int kv = (i & 3) << 2;
            float4 v = *reinterpret_cast<const float4*>(x + (size_t)(mb + m) * 1104 + kt + kv);
            sa[kv + 0][m] = v.x; sa[kv + 1][m] = v.y;
            sa[kv + 2][m] = v.z; sa[kv + 3][m] = v.w;
        }
        // load B tile duplicated (cols 70,71 zero)
        for (int i = tid; i < 16 * 72; i += 192) {
            int k = i / 72, n = i % 72;
            float v = (n < 70) ? g_wr[(kt + k) * 70 + n] : 0.f;
            sb[k][n] = make_float2(v, v);
        }
        __syncthreads();
        #pragma unroll
        for (int kk = 0; kk < 16; kk++) {
            float4 a0 = *reinterpret_cast<const float4*>(&sa[kk][m0]);
            float4 a1 = *reinterpret_cast<const float4*>(&sa[kk][m0 + 4]);
            float2 ap[4] = { make_float2(a0.x, a0.y), make_float2(a0.z, a0.w),
                             make_float2(a1.x, a1.y), make_float2(a1.z, a1.w) };
            __align__(16) float2 bv[6];
            *reinterpret_cast<float4*>(&bv[0]) = *reinterpret_cast<const float4*>(&sb[kk][n0]);
            *reinterpret_cast<float4*>(&bv[2]) = *reinterpret_cast<const float4*>(&sb[kk][n0 + 2]);
            *reinterpret_cast<float4*>(&bv[4]) = *reinterpret_cast<const float4*>(&sb[kk][n0 + 4]);
            #pragma unroll
            for (int p = 0; p < 4; p++)
                #pragma unroll
                for (int j = 0; j < 6; j++)
                    acc[p][j] = ffma2(ap[p], bv[j], acc[p][j]);
        }
        __syncthreads();
    }
    #pragma unroll
    for (int p = 0; p < 4; p++) {
        int m = mb + m0 + 2 * p;
        #pragma unroll
        for (int j = 0; j < 6; j++) {
            int n = n0 + j;
            if (n < 70) {
                g_e[(size_t)m * 70 + n]       = acc[p][j].x;
                g_e[(size_t)(m + 1) * 70 + n] = acc[p][j].y;
            }
        }
    }
}

// ---------------- K2: xg = e(65536x70) @ w_ih^T(70x280) + (b_ih+b_hh) ----------------
// BM=64, BN=70 (grid.y = 4 gate chunks), full K=70 in smem, 160 threads, tile 4x7
__global__ __launch_bounds__(160) void k_xggemm(const float* __restrict__ wih,
                                                const float* __restrict__ bih,
                                                const float* __restrict__ bhh) {
    __shared__ float se[70][66];   // e^T  [k][m]
    __shared__ float sw[70][71];   // w^T  [k][g]
    const int tid = threadIdx.x;
    const int mb = blockIdx.x * 64;
    const int gbase = blockIdx.y * 70;
    const int mg = tid / 10, ng = tid % 10;
    const int m0 = mg * 4, n0 = ng * 7;

    for (int i = tid; i < 64 * 70; i += 160) {
        int m = i / 70, k = i % 70;
        se[k][m] = g_e[(size_t)(mb + m) * 70 + k];
    }
    for (int i = tid; i < 70 * 70; i += 160) {
        int j = i / 70, k = i % 70;
        sw[k][j] = wih[(gbase + j) * 70 + k];
    }
    float acc[4][7];
    #pragma unroll
    for (int a = 0; a < 4; a++)
        #pragma unroll
        for (int c = 0; c < 7; c++) acc[a][c] = 0.f;
    __syncthreads();

    #pragma unroll 2
    for (int k = 0; k < 70; k++) {
        float av[4], wv[7];
        #pragma unroll
        for (int a = 0; a < 4; a++) av[a] = se[k][m0 + a];
        #pragma unroll
        for (int c = 0; c < 7; c++) wv[c] = sw[k][n0 + c];
        #pragma unroll
        for (int a = 0; a < 4; a++)
            #pragma unroll
            for (int c = 0; c < 7; c++) acc[a][c] += av[a] * wv[c];
    }
    float bs[7];
    #pragma unroll
    for (int c = 0; c < 7; c++) bs[c] = bih[gbase + n0 + c] + bhh[gbase + n0 + c];
    #pragma unroll
    for (int a = 0; a < 4; a++)
        #pragma unroll
        for (int c = 0; c < 7; c++)
            g_xg[(size_t)(mb + m0 + a) * 280 + gbase + n0 + c] = acc[a][c] + bs[c];
}

// ---------------- K3: LSTM recurrence, 1 CTA per batch, Whh rows in registers ----------------
__global__ __launch_bounds__(288) void k_lstm(const float* __restrict__ whh) {
    __shared__ float s_h[72];     // hidden state (padded, [70..71]=0)
    __shared__ float s_g[280];    // post-activation gates
    const int b = blockIdx.x;
    const int r = threadIdx.x;
    const float* xgb = g_xg + (size_t)b * 512 * 280;

    float2 w[35];
    if (r < 280) {
        #pragma unroll
        for (int k = 0; k < 35; k++)
            w[k] = *reinterpret_cast<const float2*>(whh + r * 70 + 2 * k);
    }
    if (r < 72) s_h[r] = 0.f;
    float c = 0.f;
    float xcur = (r < 280) ? xgb[r] : 0.f;
    __syncthreads();

    for (int t = 0; t < 512; t++) {
        // gate pre-activation: xg_t[r] + Whh[r,:] . h  (f32x2, k-pairs)
        float2 acc = make_float2(0.f, 0.f);
        #pragma unroll
        for (int k = 0; k < 35; k++) {
            float2 hv = *reinterpret_cast<const float2*>(&s_h[2 * k]);
            acc = ffma2(w[k], hv, acc);
        }
        // prefetch next timestep's xg (latency hidden across barrier/compute)
        float xnext = 0.f;
        if (r < 280 && t < 511) xnext = xgb[(size_t)(t + 1) * 280 + r];

        if (r < 280) {
            float gate = xcur + acc.x + acc.y;
            float a;
            if (r < 140)      a = sigmoidf_(gate);   // i, f
            else if (r < 210) a = tanhf_(gate);      // g
            else              a = sigmoidf_(gate);   // o
            s_g[r] = a;
        }
        __syncthreads();
        if (r < 70) {
            float i = s_g[r], f = s_g[70 + r], g = s_g[140 + r], o = s_g[210 + r];
            c = f * c + i * g;
            float h = o * tanhf_(c);
            s_h[r] = h;
            g_hs[((size_t)b * 512 + t) * 70 + r] = h;
        }
        __syncthreads();
        xcur = xnext;
    }
}

// ---------------- K4: attention energies: relu(h@w1^T+b1)@w2^T+b2 ----------------
__global__ __launch_bounds__(256) void k_energy(const float* __restrict__ w1,
                                                const float* __restrict__ b1,
                                                const float* __restrict__ w2,
                                                const float* __restrict__ b2) {
    __shared__ float s_w1[64][76];  // padded rows (cols 70..75 = 0), stride 76
    __shared__ float s_hr[8][72];
    const int tid = threadIdx.x;
    for (int i = tid; i < 64 * 70; i += 256) { int j = i / 70, k = i % 70; s_w1[j][k] = w1[i]; }
    for (int i = tid; i < 64 * 6;  i += 256) { int j = i / 6,  k = 70 + i % 6; s_w1[j][k] = 0.f; }
    const int wi = tid >> 5, lane = tid & 31;
    const int row = blockIdx.x * 8 + wi;                       // 8192*8 = 65536
    const float* hr = g_hs + (size_t)row * 70;
    for (int k = lane; k < 70; k += 32) s_hr[wi][k] = hr[k];
    if (lane < 2) s_hr[wi][70 + lane] = 0.f;
    __syncthreads();

    float sum = 0.f;
    #pragma unroll
    for (int jo = 0; jo < 2; jo++) {
        int jj = lane + 32 * jo;
        float4 acc4 = make_float4(0.f, 0.f, 0.f, 0.f);
        #pragma unroll
        for (int q = 0; q < 18; q++) {
            float4 wv = *reinterpret_cast<const float4*>(&s_w1[jj][4 * q]);
            float4 hv = *reinterpret_cast<const float4*>(&s_hr[wi][4 * q]);
            acc4.x += wv.x * hv.x; acc4.y += wv.y * hv.y;
            acc4.z += wv.z * hv.z; acc4.w += wv.w * hv.w;
        }
        float hjv = acc4.x + acc4.y + acc4.z + acc4.w + b1[jj];
        hjv = fmaxf(hjv, 0.f);
        sum += hjv * w2[jj];
    }
    #pragma unroll
    for (int o = 16; o > 0; o >>= 1) sum += __shfl_xor_sync(0xffffffffu, sum, o);
    if (lane == 0) g_energy[row] = sum + b2[0];
}

// ---------------- K5: softmax over S, pooled, fc, final softmax ----------------
__global__ __launch_bounds__(280) void k_finish(const float* __restrict__ fcw,
                                                const float* __restrict__ fcb,
                                                float* __restrict__ out) {
    __shared__ float se[512];
    __shared__ float sr[512];
    __shared__ float s_pool[4][70];
    __shared__ float s_pl[70];
    __shared__ float s_lg[3];
    const int tid = threadIdx.x;
    const int b = blockIdx.x;

    for (int i = tid; i < 512; i += 280) { float v = g_energy[b * 512 + i]; se[i] = v; sr[i] = v; }
    __syncthreads();
    for (int st = 256; st > 0; st >>= 1) {
        for (int i = tid; i < st; i += 280) sr[i] = fmaxf(sr[i], sr[i + st]);
        __syncthreads();
    }
    float mx = sr[0];
    __syncthreads();
    for (int i = tid; i < 512; i += 280) { float ev = __expf(se[i] - mx); se[i] = ev; sr[i] = ev; }
    __syncthreads();
    for (int st = 256; st > 0; st >>= 1) {
        for (int i = tid; i < st; i += 280) sr[i] += sr[i + st];
        __syncthreads();
    }
    float inv = 1.0f / sr[0];

    const int h = tid % 70, ch = tid / 70;   // 280 = 4 chunks x 70
    float p = 0.f;
    const float* base = g_hs + (size_t)b * 512 * 70;
    for (int s = ch; s < 512; s += 4) p += base[(size_t)s * 70 + h] * se[s];
    s_pool[ch][h] = p;
    __syncthreads();
    if (ch == 0) s_pl[h] = (s_pool[0][h] + s_pool[1][h] + s_pool[2][h] + s_pool[3][h]) * inv;
    __syncthreads();
    if (tid < 3) {
        float lg = fcb[tid];
        for (int k = 0; k < 70; k++) lg += s_pl[k] * fcw[tid * 70 + k];
        s_lg[tid] = lg;
    }
    __syncthreads();
    if (tid < 3) {
        float m = fmaxf(s_lg[0], fmaxf(s_lg[1], s_lg[2]));
        float e0 = __expf(s_lg[0] - m), e1 = __expf(s_lg[1] - m), e2 = __expf(s_lg[2] - m);
        float ev = (tid == 0) ? e0 : ((tid == 1) ? e1 : e2);
        out[b * 3 + tid] = ev / (e0 + e1 + e2);
    }
}

// ---------------- launch ----------------
extern "C" void kernel_launch(void* const* d_in, const int* in_sizes, int n_in,
                              void* d_out, int out_size) {
    const float* x   = (const float*)d_in[0];
    const float* ew  = (const float*)d_in[1];
    const float* wih = (const float*)d_in[2];
    const float* whh = (const float*)d_in[3];
    const float* bih = (const float*)d_in[4];
    const float* bhh = (const float*)d_in[5];
    const float* aw1 = (const float*)d_in[6];
    const float* ab1 = (const float*)d_in[7];
    const float* aw2 = (const float*)d_in[8];
    const float* ab2 = (const float*)d_in[9];
    const float* fcw = (const float*)d_in[10];
    const float* fcb = (const float*)d_in[11];
    float* out = (float*)d_out;

    k_renorm<<<138, 256>>>(ew);
    k_egemm<<<512, 192>>>(x);
    k_xggemm<<<dim3(1024, 4), 160>>>(wih, bih, bhh);
    k_lstm<<<128, 288>>>(whh);
    k_energy<<<8192, 256>>>(aw1, ab1, aw2, ab2);
    k_finish<<<128, 280>>>(fcw, fcb, out);
}